// round 1
// baseline (speedup 1.0000x reference)
#include <cuda_runtime.h>
#include <cuda_bf16.h>

#define NU 200000
#define NI 100000
#define NT 300000          // NU + NI
#define D  64
#define NE 4000000
#define NB ((NT + 1023) / 1024)   // scan blocks = 293

// -------- device scratch (no allocations allowed) --------
__device__ float g_h [NT * D];     // ping
__device__ float g_hn[NT * D];     // pong
__device__ int   g_deg[NT];
__device__ int   g_pos[NT];
__device__ float g_dinv[NT];
__device__ int   g_rowptr[NT + 1];
__device__ int   g_bsum[NB];
__device__ int   g_col[NE];        // dst, CSR-ordered by src
__device__ float g_w  [NE];        // edge weight, CSR-ordered

// -------- build: degree histogram --------
__global__ void k_zero() {
    int i = blockIdx.x * blockDim.x + threadIdx.x;
    if (i < NT) { g_deg[i] = 0; g_pos[i] = 0; }
}

__global__ void k_hist(const int4* __restrict__ src4) {
    int i = blockIdx.x * blockDim.x + threadIdx.x;
    if (i < NE / 4) {
        int4 s = src4[i];
        atomicAdd(&g_deg[s.x], 1);
        atomicAdd(&g_deg[s.y], 1);
        atomicAdd(&g_deg[s.z], 1);
        atomicAdd(&g_deg[s.w], 1);
    }
}

__global__ void k_dinv() {
    int i = blockIdx.x * blockDim.x + threadIdx.x;
    if (i < NT) g_dinv[i] = rsqrtf((float)g_deg[i] + 1e-8f);
}

// -------- build: 3-phase exclusive scan of deg -> rowptr --------
__global__ void k_scanA() {  // 1024 threads/block: block-local exclusive scan + block total
    __shared__ int ws[32];
    int i = blockIdx.x * 1024 + threadIdx.x;
    int v = (i < NT) ? g_deg[i] : 0;
    int lane = threadIdx.x & 31, wid = threadIdx.x >> 5;
    int x = v;
    #pragma unroll
    for (int o = 1; o < 32; o <<= 1) {
        int y = __shfl_up_sync(0xffffffffu, x, o);
        if (lane >= o) x += y;
    }
    if (lane == 31) ws[wid] = x;
    __syncthreads();
    if (wid == 0) {
        int s = ws[lane];
        #pragma unroll
        for (int o = 1; o < 32; o <<= 1) {
            int y = __shfl_up_sync(0xffffffffu, s, o);
            if (lane >= o) s += y;
        }
        ws[lane] = s;
    }
    __syncthreads();
    int excl = x - v + (wid > 0 ? ws[wid - 1] : 0);
    if (i < NT) g_rowptr[i] = excl;
    if (threadIdx.x == 1023) g_bsum[blockIdx.x] = ws[31];
}

__global__ void k_scanB() {  // single block of 512: exclusive scan of block sums
    __shared__ int ws[16];
    int t = threadIdx.x;
    int v = (t < NB) ? g_bsum[t] : 0;
    int lane = t & 31, wid = t >> 5;
    int x = v;
    #pragma unroll
    for (int o = 1; o < 32; o <<= 1) {
        int y = __shfl_up_sync(0xffffffffu, x, o);
        if (lane >= o) x += y;
    }
    if (lane == 31) ws[wid] = x;
    __syncthreads();
    if (wid == 0) {
        int s = (lane < 16) ? ws[lane] : 0;
        #pragma unroll
        for (int o = 1; o < 32; o <<= 1) {
            int y = __shfl_up_sync(0xffffffffu, s, o);
            if (lane >= o) s += y;
        }
        if (lane < 16) ws[lane] = s;
    }
    __syncthreads();
    int excl = x - v + (wid > 0 ? ws[wid - 1] : 0);
    if (t < NB) g_bsum[t] = excl;
    if (t == 0) g_rowptr[NT] = ws[15];   // = NE
}

__global__ void k_scanC() {
    int i = blockIdx.x * blockDim.x + threadIdx.x;
    if (i < NT) g_rowptr[i] += g_bsum[i >> 10];
}

// -------- build: scatter edges into CSR, fuse weight computation --------
__global__ void k_scatter(const int* __restrict__ src, const int* __restrict__ dst) {
    int e = blockIdx.x * blockDim.x + threadIdx.x;
    if (e < NE) {
        int s = src[e], d = dst[e];
        int p = atomicAdd(&g_pos[s], 1);
        int idx = g_rowptr[s] + p;
        g_col[idx] = d;
        g_w[idx] = g_dinv[s] * g_dinv[d];
    }
}

// -------- init: h = x, out = 0.25 * x --------
__global__ void k_init(const float4* __restrict__ uw, const float4* __restrict__ iw,
                       float4* __restrict__ out) {
    int i = blockIdx.x * blockDim.x + threadIdx.x;
    const int NU4 = NU * (D / 4);
    const int NT4 = NT * (D / 4);
    if (i < NT4) {
        float4 v = (i < NU4) ? uw[i] : iw[i - NU4];
        ((float4*)g_h)[i] = v;
        out[i] = make_float4(0.25f * v.x, 0.25f * v.y, 0.25f * v.z, 0.25f * v.w);
    }
}

// -------- SpMM: one warp per row, lane owns float2 of dims [2l,2l+1] --------
__global__ void __launch_bounds__(256) k_spmm(int parity, float2* __restrict__ out) {
    int gw = (blockIdx.x * 256 + threadIdx.x) >> 5;
    if (gw >= NT) return;
    int lane = threadIdx.x & 31;

    const float2* __restrict__ h  = (const float2*)(parity ? g_hn : g_h);
    float2*       __restrict__ hn = (float2*)      (parity ? g_h  : g_hn);

    int beg = g_rowptr[gw], end = g_rowptr[gw + 1];

    float sx0 = 0.f, sy0 = 0.f, sx1 = 0.f, sy1 = 0.f;
    int j = beg;
    for (; j + 4 <= end; j += 4) {
        int   c0 = g_col[j + 0], c1 = g_col[j + 1], c2 = g_col[j + 2], c3 = g_col[j + 3];
        float w0 = g_w[j + 0],   w1 = g_w[j + 1],   w2 = g_w[j + 2],   w3 = g_w[j + 3];
        float2 v0 = h[c0 * 32 + lane];
        float2 v1 = h[c1 * 32 + lane];
        float2 v2 = h[c2 * 32 + lane];
        float2 v3 = h[c3 * 32 + lane];
        sx0 += w0 * v0.x; sy0 += w0 * v0.y;
        sx1 += w1 * v1.x; sy1 += w1 * v1.y;
        sx0 += w2 * v2.x; sy0 += w2 * v2.y;
        sx1 += w3 * v3.x; sy1 += w3 * v3.y;
    }
    for (; j < end; j++) {
        int c = g_col[j]; float wj = g_w[j];
        float2 v = h[c * 32 + lane];
        sx0 += wj * v.x; sy0 += wj * v.y;
    }
    float sx = sx0 + sx1, sy = sy0 + sy1;

    int o = gw * 32 + lane;
    hn[o] = make_float2(sx, sy);
    float2 a = out[o];
    a.x += 0.25f * sx; a.y += 0.25f * sy;
    out[o] = a;
}

extern "C" void kernel_launch(void* const* d_in, const int* in_sizes, int n_in,
                              void* d_out, int out_size) {
    const float* uw  = (const float*)d_in[0];
    const float* iw  = (const float*)d_in[1];
    const int*   src = (const int*)d_in[2];
    const int*   dst = (const int*)d_in[3];
    float* out = (float*)d_out;

    // CSR build
    k_zero<<<(NT + 255) / 256, 256>>>();
    k_hist<<<(NE / 4 + 255) / 256, 256>>>((const int4*)src);
    k_dinv<<<(NT + 255) / 256, 256>>>();
    k_scanA<<<NB, 1024>>>();
    k_scanB<<<1, 512>>>();
    k_scanC<<<(NT + 1023) / 1024, 1024>>>();
    k_scatter<<<(NE + 255) / 256, 256>>>(src, dst);

    // init h = x, out = x/4
    k_init<<<(NT * (D / 4) + 255) / 256, 256>>>((const float4*)uw, (const float4*)iw,
                                                (float4*)out);

    // 3 propagation layers, ping-pong between g_h and g_hn
    int nblk = (NT * 32 + 255) / 256;
    k_spmm<<<nblk, 256>>>(0, (float2*)out);
    k_spmm<<<nblk, 256>>>(1, (float2*)out);
    k_spmm<<<nblk, 256>>>(0, (float2*)out);
}

// round 2
// speedup vs baseline: 1.2578x; 1.2578x over previous
#include <cuda_runtime.h>
#include <cuda_fp16.h>

#define NU 200000
#define NI 100000
#define NT 300000          // NU + NI
#define NE 4000000
#define NB ((NT + 1023) / 1024)   // scan blocks = 293

// -------- device scratch (no allocations allowed) --------
__device__ __half2 g_y [NT * 32];  // ping: y = dinv * h, lane owns dims [2l,2l+1]
__device__ __half2 g_yn[NT * 32];  // pong
__device__ int   g_deg[NT];
__device__ int   g_pos[NT];
__device__ float g_dinv[NT];
__device__ int   g_rowptr[NT + 1];
__device__ int   g_bsum[NB];
__device__ int   g_col[NE];        // dst, CSR-ordered by src

// -------- build: degree histogram --------
__global__ void k_zero() {
    int i = blockIdx.x * blockDim.x + threadIdx.x;
    if (i < NT) { g_deg[i] = 0; g_pos[i] = 0; }
}

__global__ void k_hist(const int4* __restrict__ src4) {
    int i = blockIdx.x * blockDim.x + threadIdx.x;
    if (i < NE / 4) {
        int4 s = src4[i];
        atomicAdd(&g_deg[s.x], 1);
        atomicAdd(&g_deg[s.y], 1);
        atomicAdd(&g_deg[s.z], 1);
        atomicAdd(&g_deg[s.w], 1);
    }
}

__global__ void k_dinv() {
    int i = blockIdx.x * blockDim.x + threadIdx.x;
    if (i < NT) g_dinv[i] = rsqrtf((float)g_deg[i] + 1e-8f);
}

// -------- build: 3-phase exclusive scan of deg -> rowptr --------
__global__ void k_scanA() {
    __shared__ int ws[32];
    int i = blockIdx.x * 1024 + threadIdx.x;
    int v = (i < NT) ? g_deg[i] : 0;
    int lane = threadIdx.x & 31, wid = threadIdx.x >> 5;
    int x = v;
    #pragma unroll
    for (int o = 1; o < 32; o <<= 1) {
        int y = __shfl_up_sync(0xffffffffu, x, o);
        if (lane >= o) x += y;
    }
    if (lane == 31) ws[wid] = x;
    __syncthreads();
    if (wid == 0) {
        int s = ws[lane];
        #pragma unroll
        for (int o = 1; o < 32; o <<= 1) {
            int y = __shfl_up_sync(0xffffffffu, s, o);
            if (lane >= o) s += y;
        }
        ws[lane] = s;
    }
    __syncthreads();
    int excl = x - v + (wid > 0 ? ws[wid - 1] : 0);
    if (i < NT) g_rowptr[i] = excl;
    if (threadIdx.x == 1023) g_bsum[blockIdx.x] = ws[31];
}

__global__ void k_scanB() {
    __shared__ int ws[16];
    int t = threadIdx.x;
    int v = (t < NB) ? g_bsum[t] : 0;
    int lane = t & 31, wid = t >> 5;
    int x = v;
    #pragma unroll
    for (int o = 1; o < 32; o <<= 1) {
        int y = __shfl_up_sync(0xffffffffu, x, o);
        if (lane >= o) x += y;
    }
    if (lane == 31) ws[wid] = x;
    __syncthreads();
    if (wid == 0) {
        int s = (lane < 16) ? ws[lane] : 0;
        #pragma unroll
        for (int o = 1; o < 32; o <<= 1) {
            int y = __shfl_up_sync(0xffffffffu, s, o);
            if (lane >= o) s += y;
        }
        if (lane < 16) ws[lane] = s;
    }
    __syncthreads();
    int excl = x - v + (wid > 0 ? ws[wid - 1] : 0);
    if (t < NB) g_bsum[t] = excl;
    if (t == 0) g_rowptr[NT] = ws[15];   // = NE
}

__global__ void k_scanC() {
    int i = blockIdx.x * blockDim.x + threadIdx.x;
    if (i < NT) g_rowptr[i] += g_bsum[i >> 10];
}

// -------- build: scatter edges into CSR (columns only, no weights) --------
__global__ void k_scatter(const int* __restrict__ src, const int* __restrict__ dst) {
    int e = blockIdx.x * blockDim.x + threadIdx.x;
    if (e < NE) {
        int s = src[e];
        int p = atomicAdd(&g_pos[s], 1);
        g_col[g_rowptr[s] + p] = dst[e];
    }
}

// -------- init: y0 = dinv * x (fp16), out = 0.25 * x --------
__global__ void k_init(const float2* __restrict__ uw, const float2* __restrict__ iw,
                       float2* __restrict__ out) {
    int i = blockIdx.x * blockDim.x + threadIdx.x;   // half2 element index
    const int NU2 = NU * 32;
    const int NT2 = NT * 32;
    if (i < NT2) {
        float2 v = (i < NU2) ? uw[i] : iw[i - NU2];
        float di = g_dinv[i >> 5];
        g_y[i] = __floats2half2_rn(di * v.x, di * v.y);
        out[i] = make_float2(0.25f * v.x, 0.25f * v.y);
    }
}

// -------- SpMM: warp per row; s = sum y[col]; h = dinv*s; y_next = dinv^2*s --------
template<int WRITE_NEXT>
__global__ void __launch_bounds__(256) k_spmm(int parity, float2* __restrict__ out) {
    int gw = (blockIdx.x * 256 + threadIdx.x) >> 5;
    if (gw >= NT) return;
    int lane = threadIdx.x & 31;

    const __half2* __restrict__ y  = parity ? g_yn : g_y;
    __half2*       __restrict__ yn = parity ? g_y  : g_yn;

    int beg = g_rowptr[gw], end = g_rowptr[gw + 1];

    float sx0 = 0.f, sy0 = 0.f, sx1 = 0.f, sy1 = 0.f;
    for (int base = beg; base < end; base += 32) {
        int n = end - base; if (n > 32) n = 32;
        int myc = (base + lane < end) ? g_col[base + lane] : 0;
        int k = 0;
        for (; k + 4 <= n; k += 4) {
            int c0 = __shfl_sync(0xffffffffu, myc, k + 0);
            int c1 = __shfl_sync(0xffffffffu, myc, k + 1);
            int c2 = __shfl_sync(0xffffffffu, myc, k + 2);
            int c3 = __shfl_sync(0xffffffffu, myc, k + 3);
            float2 v0 = __half22float2(y[c0 * 32 + lane]);
            float2 v1 = __half22float2(y[c1 * 32 + lane]);
            float2 v2 = __half22float2(y[c2 * 32 + lane]);
            float2 v3 = __half22float2(y[c3 * 32 + lane]);
            sx0 += v0.x; sy0 += v0.y;
            sx1 += v1.x; sy1 += v1.y;
            sx0 += v2.x; sy0 += v2.y;
            sx1 += v3.x; sy1 += v3.y;
        }
        for (; k < n; k++) {
            int c = __shfl_sync(0xffffffffu, myc, k);
            float2 v = __half22float2(y[c * 32 + lane]);
            sx0 += v.x; sy0 += v.y;
        }
    }
    float s_x = sx0 + sx1, s_y = sy0 + sy1;

    float di = g_dinv[gw];
    float hx = di * s_x, hy = di * s_y;       // h contribution
    int o = gw * 32 + lane;
    if (WRITE_NEXT)
        yn[o] = __floats2half2_rn(di * hx, di * hy);   // dinv^2 * s
    float2 a = out[o];
    a.x += 0.25f * hx; a.y += 0.25f * hy;
    out[o] = a;
}

extern "C" void kernel_launch(void* const* d_in, const int* in_sizes, int n_in,
                              void* d_out, int out_size) {
    const float* uw  = (const float*)d_in[0];
    const float* iw  = (const float*)d_in[1];
    const int*   src = (const int*)d_in[2];
    const int*   dst = (const int*)d_in[3];
    float* out = (float*)d_out;

    // CSR build
    k_zero<<<(NT + 255) / 256, 256>>>();
    k_hist<<<(NE / 4 + 255) / 256, 256>>>((const int4*)src);
    k_dinv<<<(NT + 255) / 256, 256>>>();
    k_scanA<<<NB, 1024>>>();
    k_scanB<<<1, 512>>>();
    k_scanC<<<(NT + 1023) / 1024, 1024>>>();
    k_scatter<<<(NE + 255) / 256, 256>>>(src, dst);

    // init y0 = dinv*x (fp16), out = x/4
    k_init<<<(NT * 32 + 255) / 256, 256>>>((const float2*)uw, (const float2*)iw,
                                           (float2*)out);

    // 3 propagation layers, ping-pong y between g_y and g_yn
    int nblk = (NT * 32 + 255) / 256;
    k_spmm<1><<<nblk, 256>>>(0, (float2*)out);
    k_spmm<1><<<nblk, 256>>>(1, (float2*)out);
    k_spmm<0><<<nblk, 256>>>(0, (float2*)out);
}